// round 10
// baseline (speedup 1.0000x reference)
#include <cuda_runtime.h>
#include <cuda_bf16.h>
#include <cstdint>

// ---------------------------------------------------------------------------
// GraphSAGE on GB300 (base sm_103 target: no tcgen05) —
// bf16-split mma.sync GEMM + CSR mean aggregation.
//
//   h, agg kept as bf16 hi/lo plane pairs (hi+lo ~= fp32, err ~2^-18).
//   GEMM: mma.sync.m16n8k16 bf16, fp32 accum, 3-product split
//         (hi*hi + hi*lo + lo*hi), dual operand fused as K-chunk loop.
//   R9 changes: GEMM BN 64->128 (halves A re-reads, 16:6 MMA:LDSM),
//   cp.async.cg smem loaders, aggregate edge-loop unroll x2.
// ---------------------------------------------------------------------------

#define NMAX 100032
#define EMAX 3200000
#define D    256

// ---- static device scratch (no runtime allocation) ----
__device__ __align__(16) __nv_bfloat16 g_hiP[3][(size_t)NMAX * D];  // 0,1 = h ping-pong, 2 = agg
__device__ __align__(16) __nv_bfloat16 g_loP[3][(size_t)NMAX * D];
__device__ __align__(16) unsigned g_Whi[7 * 32768];   // 7 weight mats as bf16x2
__device__ __align__(16) unsigned g_Wlo[7 * 32768];
__device__ int   g_deg[NMAX];
__device__ int   g_rowptr[NMAX + 1];
__device__ int   g_cursor[NMAX];
__device__ float g_inv[NMAX];
__device__ int   g_col[EMAX];
__device__ int   g_bsum[1024];
__device__ int   g_boff[1024];

// ---------------------------------------------------------------------------
// helpers
// ---------------------------------------------------------------------------
__device__ __forceinline__ uint32_t smem_to_u32(const void* p) {
    uint32_t a;
    asm("{ .reg .u64 t; cvta.to.shared.u64 t, %1; cvt.u32.u64 %0, t; }"
        : "=r"(a) : "l"(p));
    return a;
}

__device__ __forceinline__ void ldsm4(uint32_t addr, uint32_t& r0, uint32_t& r1,
                                      uint32_t& r2, uint32_t& r3) {
    asm volatile("ldmatrix.sync.aligned.m8n8.x4.shared.b16 {%0,%1,%2,%3}, [%4];"
                 : "=r"(r0), "=r"(r1), "=r"(r2), "=r"(r3) : "r"(addr));
}

__device__ __forceinline__ void mma16816(float* c, uint32_t a0, uint32_t a1,
                                         uint32_t a2, uint32_t a3,
                                         uint32_t b0, uint32_t b1) {
    asm volatile(
        "mma.sync.aligned.m16n8k16.row.col.f32.bf16.bf16.f32 "
        "{%0,%1,%2,%3}, {%4,%5,%6,%7}, {%8,%9}, {%0,%1,%2,%3};"
        : "+f"(c[0]), "+f"(c[1]), "+f"(c[2]), "+f"(c[3])
        : "r"(a0), "r"(a1), "r"(a2), "r"(a3), "r"(b0), "r"(b1));
}

__device__ __forceinline__ void cpasync16(uint32_t saddr, const void* gaddr) {
    asm volatile("cp.async.cg.shared.global [%0], [%1], 16;"
                 :: "r"(saddr), "l"(gaddr));
}
__device__ __forceinline__ void cpasync_commit_wait() {
    asm volatile("cp.async.commit_group;" ::: "memory");
    asm volatile("cp.async.wait_group 0;" ::: "memory");
}

// split one fp32 pair into bf16x2 hi + bf16x2 lo
__device__ __forceinline__ void split2u(float a, float b, unsigned& hi, unsigned& lo) {
    __nv_bfloat162 h = __floats2bfloat162_rn(a, b);
    float2 hf = __bfloat1622float2(h);
    __nv_bfloat162 l = __floats2bfloat162_rn(a - hf.x, b - hf.y);
    hi = *reinterpret_cast<unsigned*>(&h);
    lo = *reinterpret_cast<unsigned*>(&l);
}

// ---------------------------------------------------------------------------
// CSR construction
// ---------------------------------------------------------------------------
__global__ void zero_deg(int n) {
    int i = blockIdx.x * blockDim.x + threadIdx.x;
    if (i < n) g_deg[i] = 0;
}

__global__ void count_deg(const int* __restrict__ dst, int E) {
    int i = blockIdx.x * blockDim.x + threadIdx.x;
    if (i < E) atomicAdd(&g_deg[dst[i]], 1);
}

__global__ void block_sums(int n) {
    int i = blockIdx.x * 256 + threadIdx.x;
    int v = (i < n) ? g_deg[i] : 0;
#pragma unroll
    for (int off = 16; off > 0; off >>= 1)
        v += __shfl_down_sync(0xFFFFFFFF, v, off);
    __shared__ int ws[8];
    int lane = threadIdx.x & 31, warp = threadIdx.x >> 5;
    if (lane == 0) ws[warp] = v;
    __syncthreads();
    if (threadIdx.x == 0) {
        int s = 0;
#pragma unroll
        for (int w = 0; w < 8; w++) s += ws[w];
        g_bsum[blockIdx.x] = s;
    }
}

__global__ void scan_bsums(int nb, int n, int E) {
    __shared__ int s[1024];
    int t = threadIdx.x;
    int v = (t < nb) ? g_bsum[t] : 0;
    s[t] = v;
    __syncthreads();
    for (int off = 1; off < 1024; off <<= 1) {
        int u = (t >= off) ? s[t - off] : 0;
        __syncthreads();
        s[t] += u;
        __syncthreads();
    }
    g_boff[t] = s[t] - v;   // exclusive
    if (t == 0) g_rowptr[n] = E;
}

__global__ void fill_row(int n) {
    int i = blockIdx.x * 256 + threadIdx.x;
    int lane = threadIdx.x & 31, warp = threadIdx.x >> 5;
    int d = (i < n) ? g_deg[i] : 0;
    int inc = d;
#pragma unroll
    for (int off = 1; off < 32; off <<= 1) {
        int u = __shfl_up_sync(0xFFFFFFFF, inc, off);
        if (lane >= off) inc += u;
    }
    __shared__ int wsum[8];
    if (lane == 31) wsum[warp] = inc;
    __syncthreads();
    int wbase = 0;
#pragma unroll
    for (int w = 0; w < 8; w++)
        if (w < warp) wbase += wsum[w];
    int ex = g_boff[blockIdx.x] + wbase + inc - d;
    if (i < n) {
        g_rowptr[i] = ex;
        g_cursor[i] = ex;
        g_inv[i]    = 1.0f / (float)max(d, 1);
    }
}

__global__ void fill_csr(const int* __restrict__ src,
                         const int* __restrict__ dst, int E) {
    int i = blockIdx.x * blockDim.x + threadIdx.x;
    if (i < E) {
        int d = dst[i];
        int p = atomicAdd(&g_cursor[d], 1);
        g_col[p] = src[i];
    }
}

// ---------------------------------------------------------------------------
// Weight conversion: 7 fp32 [256,256] matrices -> bf16 hi/lo planes
// ---------------------------------------------------------------------------
struct WPtrs { const float* p[7]; };

__global__ void convert_w(WPtrs wp) {
    int i = blockIdx.x * blockDim.x + threadIdx.x;
    if (i >= 7 * 32768) return;
    int w = i >> 15;
    int e = (i & 32767) * 2;
    const float* src = wp.p[w];
    unsigned hi, lo;
    split2u(__ldg(&src[e]), __ldg(&src[e + 1]), hi, lo);
    g_Whi[i] = hi;
    g_Wlo[i] = lo;
}

// ---------------------------------------------------------------------------
// h0 = emb[x] -> hi/lo planes of buffer 0
// ---------------------------------------------------------------------------
__global__ void gather_emb(const int* __restrict__ x,
                           const float* __restrict__ emb, int n) {
    int i = blockIdx.x * blockDim.x + threadIdx.x;
    if (i >= n * 32) return;
    int node = i >> 5, q = i & 31;
    const float4* src = (const float4*)(emb + (size_t)__ldg(&x[node]) * D) + q * 2;
    float4 f0 = __ldg(src), f1 = __ldg(src + 1);
    unsigned h0, l0, h1, l1, h2, l2, h3, l3;
    split2u(f0.x, f0.y, h0, l0); split2u(f0.z, f0.w, h1, l1);
    split2u(f1.x, f1.y, h2, l2); split2u(f1.z, f1.w, h3, l3);
    ((uint4*)g_hiP[0])[(size_t)node * 32 + q] = make_uint4(h0, h1, h2, h3);
    ((uint4*)g_loP[0])[(size_t)node * 32 + q] = make_uint4(l0, l1, l2, l3);
}

// ---------------------------------------------------------------------------
// Mean aggregation: warp per node, fp32 register accum, hi+lo planes.
// Edge loop unrolled x2 for MLP.
// ---------------------------------------------------------------------------
__global__ void __launch_bounds__(256)
aggregate(int selH, int n) {
    int w = (blockIdx.x * blockDim.x + threadIdx.x) >> 5;
    if (w >= n) return;
    int lane = threadIdx.x & 31;
    const uint4* hv = (const uint4*)g_hiP[selH];
    const uint4* lv = (const uint4*)g_loP[selH];
    int s = g_rowptr[w], e = g_rowptr[w + 1];
    float acc[8] = {0.f, 0.f, 0.f, 0.f, 0.f, 0.f, 0.f, 0.f};
    int t = s;
    for (; t + 2 <= e; t += 2) {
        size_t j0 = (size_t)__ldg(&g_col[t])     * 32 + lane;
        size_t j1 = (size_t)__ldg(&g_col[t + 1]) * 32 + lane;
        uint4 h0 = __ldg(&hv[j0]);
        uint4 l0 = __ldg(&lv[j0]);
        uint4 h1 = __ldg(&hv[j1]);
        uint4 l1 = __ldg(&lv[j1]);
        const unsigned* p0h = (const unsigned*)&h0;
        const unsigned* p0l = (const unsigned*)&l0;
        const unsigned* p1h = (const unsigned*)&h1;
        const unsigned* p1l = (const unsigned*)&l1;
#pragma unroll
        for (int p = 0; p < 4; p++) {
            float2 a = __bfloat1622float2(*(const __nv_bfloat162*)&p0h[p]);
            float2 b = __bfloat1622float2(*(const __nv_bfloat162*)&p0l[p]);
            float2 c = __bfloat1622float2(*(const __nv_bfloat162*)&p1h[p]);
            float2 d = __bfloat1622float2(*(const __nv_bfloat162*)&p1l[p]);
            acc[p * 2]     += (a.x + b.x) + (c.x + d.x);
            acc[p * 2 + 1] += (a.y + b.y) + (c.y + d.y);
        }
    }
    if (t < e) {
        size_t j = (size_t)__ldg(&g_col[t]) * 32 + lane;
        uint4 h4 = __ldg(&hv[j]);
        uint4 l4 = __ldg(&lv[j]);
        const unsigned* hp = (const unsigned*)&h4;
        const unsigned* lp = (const unsigned*)&l4;
#pragma unroll
        for (int p = 0; p < 4; p++) {
            float2 fh = __bfloat1622float2(*(const __nv_bfloat162*)&hp[p]);
            float2 fl = __bfloat1622float2(*(const __nv_bfloat162*)&lp[p]);
            acc[p * 2]     += fh.x + fl.x;
            acc[p * 2 + 1] += fh.y + fl.y;
        }
    }
    float iv = g_inv[w];
    unsigned ho[4], lo[4];
#pragma unroll
    for (int p = 0; p < 4; p++)
        split2u(acc[p * 2] * iv, acc[p * 2 + 1] * iv, ho[p], lo[p]);
    ((uint4*)g_hiP[2])[(size_t)w * 32 + lane] = make_uint4(ho[0], ho[1], ho[2], ho[3]);
    ((uint4*)g_loP[2])[(size_t)w * 32 + lane] = make_uint4(lo[0], lo[1], lo[2], lo[3]);
}

// ---------------------------------------------------------------------------
// mma.sync bf16-split GEMM, tile M=128 N=128, K chunks of 64.
//   LAYER=true : C = agg@Wl^T + h@Wr^T + bias, PReLU, write hi/lo planes.
//   LAYER=false: C = h@Wout^T + bias, write fp32 to Cext.
// 8 warps as 4(M) x 2(N); warp tile 32x64. cp.async.cg loaders.
// Smem rows are 128B with 16B XOR swizzle (conflict-free LDSM).
// ---------------------------------------------------------------------------
static constexpr int SM_AHI = 0;
static constexpr int SM_ALO = 16384;
static constexpr int SM_WHI = 32768;
static constexpr int SM_WLO = 49152;
static constexpr int SMEM_TOTAL = 65536;

template <bool LAYER>
__global__ void __launch_bounds__(256)
gemm_mma(int selA2, int selOut, int ws1, int ws2,
         const float* __restrict__ bias, const float* __restrict__ slope,
         float* __restrict__ Cext, int n) {
    extern __shared__ __align__(16) char smem[];
    uint32_t sb = smem_to_u32(smem);
    int tid = threadIdx.x, wid = tid >> 5, lane = tid & 31;
    int warpM = wid & 3, warpN = wid >> 2;     // 4 x 2
    int m0 = blockIdx.x * 128, o0 = blockIdx.y * 128;

    float acc[2][8][4];
#pragma unroll
    for (int a = 0; a < 2; a++)
#pragma unroll
        for (int b = 0; b < 8; b++)
#pragma unroll
            for (int c = 0; c < 4; c++) acc[a][b][c] = 0.f;

    // ldmatrix lane addressing
    int aRow = warpM * 32 + (lane & 15);
    int bRow = warpN * 64 + (lane & 15);
    int kbL  = (lane >> 4) * 16;
    uint32_t aXor = (uint32_t)((aRow & 7) << 4);
    uint32_t bXor = (uint32_t)((bRow & 7) << 4);

    // loader thread mapping (row, 16B column j)
    int ldRow = tid >> 1;            // 0..127
    int ldJ0  = (tid & 1) * 4;       // 0 or 4 (each thread does 4 consecutive j)

    const int NC = LAYER ? 8 : 4;
    for (int c = 0; c < NC; c++) {
        int op = LAYER ? (c >> 2) : 0;
        int kk = (c & 3) * 64;
        const __nv_bfloat16* Ah;
        const __nv_bfloat16* Al;
        if (LAYER && op == 0) { Ah = g_hiP[2];     Al = g_loP[2]; }
        else                  { Ah = g_hiP[selA2]; Al = g_loP[selA2]; }
        int ws = op ? ws2 : ws1;
        const __nv_bfloat16* Wh = (const __nv_bfloat16*)g_Whi + (size_t)ws * 65536;
        const __nv_bfloat16* Wl = (const __nv_bfloat16*)g_Wlo + (size_t)ws * 65536;

        __syncthreads();   // all warps done reading previous chunk's tiles
        // A tile: 128 rows x 128B per plane; W tile: 128 rows x 128B per plane
        {
            int garow = min(m0 + ldRow, n - 1);
            int gwrow = o0 + ldRow;
#pragma unroll
            for (int u = 0; u < 4; u++) {
                int j = ldJ0 + u;
                uint32_t so = (uint32_t)(ldRow * 128 + ((j * 16) ^ ((ldRow & 7) << 4)));
                size_t ga = (size_t)garow * D + kk + j * 8;
                size_t gw = (size_t)gwrow * D + kk + j * 8;
                cpasync16(sb + SM_AHI + so, Ah + ga);
                cpasync16(sb + SM_ALO + so, Al + ga);
                cpasync16(sb + SM_WHI + so, Wh + gw);
                cpasync16(sb + SM_WLO + so, Wl + gw);
            }
        }
        cpasync_commit_wait();
        __syncthreads();

        // 3 split products: (Ahi,Whi), (Ahi,Wlo), (Alo,Whi)
#pragma unroll
        for (int p = 0; p < 3; p++) {
            uint32_t aB = sb + (p == 2 ? SM_ALO : SM_AHI);
            uint32_t wB = sb + (p == 1 ? SM_WLO : SM_WHI);
#pragma unroll
            for (int k = 0; k < 4; k++) {
                uint32_t kb = (uint32_t)(k * 32 + kbL);
                uint32_t af[2][4], bf[4][4];
#pragma unroll
                for (int mt = 0; mt < 2; mt++)
                    ldsm4(aB + (uint32_t)((aRow + mt * 16) * 128) + (kb ^ aXor),
                          af[mt][0], af[mt][1], af[mt][2], af[mt][3]);
#pragma unroll
                for (int nt2 = 0; nt2 < 4; nt2++)
                    ldsm4(wB + (uint32_t)((bRow + nt2 * 16) * 128) + (kb ^ bXor),
                          bf[nt2][0], bf[nt2][1], bf[nt2][2], bf[nt2][3]);
#pragma unroll
                for (int mt = 0; mt < 2; mt++)
#pragma unroll
                    for (int nt2 = 0; nt2 < 4; nt2++) {
                        mma16816(acc[mt][nt2 * 2],
                                 af[mt][0], af[mt][1], af[mt][2], af[mt][3],
                                 bf[nt2][0], bf[nt2][2]);
                        mma16816(acc[mt][nt2 * 2 + 1],
                                 af[mt][0], af[mt][1], af[mt][2], af[mt][3],
                                 bf[nt2][1], bf[nt2][3]);
                    }
            }
        }
    }

    // ---- epilogue: direct stores from mma fragments ----
    int quad = lane >> 2, qt = lane & 3;
    float sl = LAYER ? __ldg(slope) : 0.f;
    float bj0[8], bj1[8];
#pragma unroll
    for (int nt = 0; nt < 8; nt++) {
        int col = o0 + warpN * 64 + nt * 8 + qt * 2;
        bj0[nt] = __ldg(&bias[col]);
        bj1[nt] = __ldg(&bias[col + 1]);
    }
#pragma unroll
    for (int mt = 0; mt < 2; mt++) {
#pragma unroll
        for (int half = 0; half < 2; half++) {
            int gr = m0 + warpM * 32 + mt * 16 + quad + half * 8;
            if (gr < n) {
#pragma unroll
                for (int nt = 0; nt < 8; nt++) {
                    float v0 = acc[mt][nt][half * 2]     + bj0[nt];
                    float v1 = acc[mt][nt][half * 2 + 1] + bj1[nt];
                    int cp = (o0 >> 1) + warpN * 32 + nt * 4 + qt;  // col-pair idx
                    if (LAYER) {
                        v0 = (v0 >= 0.f) ? v0 : sl * v0;
                        v1 = (v1 >= 0.f) ? v1 : sl * v1;
                        unsigned hi, lo;
                        split2u(v0, v1, hi, lo);
                        size_t idx = (size_t)gr * 128 + cp;
                        ((unsigned*)g_hiP[selOut])[idx] = hi;
                        ((unsigned*)g_loP[selOut])[idx] = lo;
                    } else {
                        ((float2*)Cext)[(size_t)gr * 128 + cp] = make_float2(v0, v1);
                    }
                }
            }
        }
    }
}

// ---------------------------------------------------------------------------
// Host launcher
// Inputs: 0 x(i32,N) 1 edge_index(i32,2E) 2 edge_weight(unused) 3 emb
//         4 Wl1 5 bl1 6 Wr1 7 a1  8 Wl2 9 bl2 10 Wr2 11 a2
//         12 Wl3 13 bl3 14 Wr3 15 a3  16 Wout 17 bout
// ---------------------------------------------------------------------------
extern "C" void kernel_launch(void* const* d_in, const int* in_sizes, int n_in,
                              void* d_out, int out_size) {
    const int*   x   = (const int*)d_in[0];
    const int*   ei  = (const int*)d_in[1];
    const float* emb = (const float*)d_in[3];
    int n = in_sizes[0];
    int E = in_sizes[1] / 2;
    const int* src = ei;
    const int* dst = ei + E;

    const float* bl[3] = {(const float*)d_in[5], (const float*)d_in[9],  (const float*)d_in[13]};
    const float* ap[3] = {(const float*)d_in[7], (const float*)d_in[11], (const float*)d_in[15]};
    const float* bout  = (const float*)d_in[17];

    cudaFuncSetAttribute(gemm_mma<true>,  cudaFuncAttributeMaxDynamicSharedMemorySize, SMEM_TOTAL);
    cudaFuncSetAttribute(gemm_mma<false>, cudaFuncAttributeMaxDynamicSharedMemorySize, SMEM_TOTAL);

    // weight slots: 0..2 = Wl1..3, 3..5 = Wr1..3, 6 = Wout
    WPtrs wp;
    wp.p[0] = (const float*)d_in[4];
    wp.p[1] = (const float*)d_in[8];
    wp.p[2] = (const float*)d_in[12];
    wp.p[3] = (const float*)d_in[6];
    wp.p[4] = (const float*)d_in[10];
    wp.p[5] = (const float*)d_in[14];
    wp.p[6] = (const float*)d_in[16];
    convert_w<<<896, 256>>>(wp);

    // CSR build (parallel 3-phase scan)
    int nb = (n + 255) / 256;
    zero_deg<<<nb, 256>>>(n);
    count_deg<<<(E + 255) / 256, 256>>>(dst, E);
    block_sums<<<nb, 256>>>(n);
    scan_bsums<<<1, 1024>>>(nb, n, E);
    fill_row<<<nb, 256>>>(n);
    fill_csr<<<(E + 255) / 256, 256>>>(src, dst, E);

    // h0 = emb[x] -> planes 0
    gather_emb<<<(n * 32 + 255) / 256, 256>>>(x, emb, n);

    dim3 gg((n + 127) / 128, 2);
    int h = 0, o = 1;
    for (int l = 0; l < 3; l++) {
        aggregate<<<((size_t)n * 32 + 255) / 256, 256>>>(h, n);
        gemm_mma<true><<<gg, 256, SMEM_TOTAL>>>(h, o, l, 3 + l, bl[l], ap[l], nullptr, n);
        int t = h; h = o; o = t;
    }
    gemm_mma<false><<<gg, 256, SMEM_TOTAL>>>(h, 0, 6, 0, bout, nullptr, (float*)d_out, n);
}

// round 11
// speedup vs baseline: 1.1067x; 1.1067x over previous
#include <cuda_runtime.h>
#include <cuda_bf16.h>
#include <cstdint>

// ---------------------------------------------------------------------------
// GraphSAGE on GB300 (base sm_103 target: no tcgen05) —
// bf16-split mma.sync GEMM + CSR mean aggregation.
//
//   h, agg kept as bf16 hi/lo plane pairs (hi+lo ~= fp32, err ~2^-18).
//   GEMM: mma.sync.m16n8k16 bf16, fp32 accum, 3-product split
//         (hi*hi + hi*lo + lo*hi), dual operand fused as K-chunk loop.
//   R10: revert R9's BN=128/cp.async GEMM (occupancy collapse, +159us);
//   keep R8 GEMM (BN=64) + parallel scan + unrolled aggregate.
// ---------------------------------------------------------------------------

#define NMAX 100032
#define EMAX 3200000
#define D    256

// ---- static device scratch (no runtime allocation) ----
__device__ __align__(16) __nv_bfloat16 g_hiP[3][(size_t)NMAX * D];  // 0,1 = h ping-pong, 2 = agg
__device__ __align__(16) __nv_bfloat16 g_loP[3][(size_t)NMAX * D];
__device__ __align__(16) unsigned g_Whi[7 * 32768];   // 7 weight mats as bf16x2
__device__ __align__(16) unsigned g_Wlo[7 * 32768];
__device__ int   g_deg[NMAX];
__device__ int   g_rowptr[NMAX + 1];
__device__ int   g_cursor[NMAX];
__device__ float g_inv[NMAX];
__device__ int   g_col[EMAX];
__device__ int   g_bsum[1024];
__device__ int   g_boff[1024];

// ---------------------------------------------------------------------------
// helpers
// ---------------------------------------------------------------------------
__device__ __forceinline__ uint32_t smem_to_u32(const void* p) {
    uint32_t a;
    asm("{ .reg .u64 t; cvta.to.shared.u64 t, %1; cvt.u32.u64 %0, t; }"
        : "=r"(a) : "l"(p));
    return a;
}

__device__ __forceinline__ void ldsm4(uint32_t addr, uint32_t& r0, uint32_t& r1,
                                      uint32_t& r2, uint32_t& r3) {
    asm volatile("ldmatrix.sync.aligned.m8n8.x4.shared.b16 {%0,%1,%2,%3}, [%4];"
                 : "=r"(r0), "=r"(r1), "=r"(r2), "=r"(r3) : "r"(addr));
}

__device__ __forceinline__ void mma16816(float* c, uint32_t a0, uint32_t a1,
                                         uint32_t a2, uint32_t a3,
                                         uint32_t b0, uint32_t b1) {
    asm volatile(
        "mma.sync.aligned.m16n8k16.row.col.f32.bf16.bf16.f32 "
        "{%0,%1,%2,%3}, {%4,%5,%6,%7}, {%8,%9}, {%0,%1,%2,%3};"
        : "+f"(c[0]), "+f"(c[1]), "+f"(c[2]), "+f"(c[3])
        : "r"(a0), "r"(a1), "r"(a2), "r"(a3), "r"(b0), "r"(b1));
}

// split one fp32 pair into bf16x2 hi + bf16x2 lo
__device__ __forceinline__ void split2u(float a, float b, unsigned& hi, unsigned& lo) {
    __nv_bfloat162 h = __floats2bfloat162_rn(a, b);
    float2 hf = __bfloat1622float2(h);
    __nv_bfloat162 l = __floats2bfloat162_rn(a - hf.x, b - hf.y);
    hi = *reinterpret_cast<unsigned*>(&h);
    lo = *reinterpret_cast<unsigned*>(&l);
}

// ---------------------------------------------------------------------------
// CSR construction
// ---------------------------------------------------------------------------
__global__ void zero_deg(int n) {
    int i = blockIdx.x * blockDim.x + threadIdx.x;
    if (i < n) g_deg[i] = 0;
}

__global__ void count_deg(const int* __restrict__ dst, int E) {
    int i = blockIdx.x * blockDim.x + threadIdx.x;
    if (i < E) atomicAdd(&g_deg[dst[i]], 1);
}

__global__ void block_sums(int n) {
    int i = blockIdx.x * 256 + threadIdx.x;
    int v = (i < n) ? g_deg[i] : 0;
#pragma unroll
    for (int off = 16; off > 0; off >>= 1)
        v += __shfl_down_sync(0xFFFFFFFF, v, off);
    __shared__ int ws[8];
    int lane = threadIdx.x & 31, warp = threadIdx.x >> 5;
    if (lane == 0) ws[warp] = v;
    __syncthreads();
    if (threadIdx.x == 0) {
        int s = 0;
#pragma unroll
        for (int w = 0; w < 8; w++) s += ws[w];
        g_bsum[blockIdx.x] = s;
    }
}

__global__ void scan_bsums(int nb, int n, int E) {
    __shared__ int s[1024];
    int t = threadIdx.x;
    int v = (t < nb) ? g_bsum[t] : 0;
    s[t] = v;
    __syncthreads();
    for (int off = 1; off < 1024; off <<= 1) {
        int u = (t >= off) ? s[t - off] : 0;
        __syncthreads();
        s[t] += u;
        __syncthreads();
    }
    g_boff[t] = s[t] - v;   // exclusive
    if (t == 0) g_rowptr[n] = E;
}

__global__ void fill_row(int n) {
    int i = blockIdx.x * 256 + threadIdx.x;
    int lane = threadIdx.x & 31, warp = threadIdx.x >> 5;
    int d = (i < n) ? g_deg[i] : 0;
    int inc = d;
#pragma unroll
    for (int off = 1; off < 32; off <<= 1) {
        int u = __shfl_up_sync(0xFFFFFFFF, inc, off);
        if (lane >= off) inc += u;
    }
    __shared__ int wsum[8];
    if (lane == 31) wsum[warp] = inc;
    __syncthreads();
    int wbase = 0;
#pragma unroll
    for (int w = 0; w < 8; w++)
        if (w < warp) wbase += wsum[w];
    int ex = g_boff[blockIdx.x] + wbase + inc - d;
    if (i < n) {
        g_rowptr[i] = ex;
        g_cursor[i] = ex;
        g_inv[i]    = 1.0f / (float)max(d, 1);
    }
}

__global__ void fill_csr(const int* __restrict__ src,
                         const int* __restrict__ dst, int E) {
    int i = blockIdx.x * blockDim.x + threadIdx.x;
    if (i < E) {
        int d = dst[i];
        int p = atomicAdd(&g_cursor[d], 1);
        g_col[p] = src[i];
    }
}

// ---------------------------------------------------------------------------
// Weight conversion: 7 fp32 [256,256] matrices -> bf16 hi/lo planes
// ---------------------------------------------------------------------------
struct WPtrs { const float* p[7]; };

__global__ void convert_w(WPtrs wp) {
    int i = blockIdx.x * blockDim.x + threadIdx.x;
    if (i >= 7 * 32768) return;
    int w = i >> 15;
    int e = (i & 32767) * 2;
    const float* src = wp.p[w];
    unsigned hi, lo;
    split2u(__ldg(&src[e]), __ldg(&src[e + 1]), hi, lo);
    g_Whi[i] = hi;
    g_Wlo[i] = lo;
}

// ---------------------------------------------------------------------------
// h0 = emb[x] -> hi/lo planes of buffer 0
// ---------------------------------------------------------------------------
__global__ void gather_emb(const int* __restrict__ x,
                           const float* __restrict__ emb, int n) {
    int i = blockIdx.x * blockDim.x + threadIdx.x;
    if (i >= n * 32) return;
    int node = i >> 5, q = i & 31;
    const float4* src = (const float4*)(emb + (size_t)__ldg(&x[node]) * D) + q * 2;
    float4 f0 = __ldg(src), f1 = __ldg(src + 1);
    unsigned h0, l0, h1, l1, h2, l2, h3, l3;
    split2u(f0.x, f0.y, h0, l0); split2u(f0.z, f0.w, h1, l1);
    split2u(f1.x, f1.y, h2, l2); split2u(f1.z, f1.w, h3, l3);
    ((uint4*)g_hiP[0])[(size_t)node * 32 + q] = make_uint4(h0, h1, h2, h3);
    ((uint4*)g_loP[0])[(size_t)node * 32 + q] = make_uint4(l0, l1, l2, l3);
}

// ---------------------------------------------------------------------------
// Mean aggregation: warp per node, fp32 register accum, hi+lo planes.
// Edge loop unrolled x2 (4 independent 16B loads in flight per lane).
// ---------------------------------------------------------------------------
__global__ void __launch_bounds__(256)
aggregate(int selH, int n) {
    int w = (blockIdx.x * blockDim.x + threadIdx.x) >> 5;
    if (w >= n) return;
    int lane = threadIdx.x & 31;
    const uint4* hv = (const uint4*)g_hiP[selH];
    const uint4* lv = (const uint4*)g_loP[selH];
    int s = g_rowptr[w], e = g_rowptr[w + 1];
    float acc[8] = {0.f, 0.f, 0.f, 0.f, 0.f, 0.f, 0.f, 0.f};
    int t = s;
    for (; t + 2 <= e; t += 2) {
        size_t j0 = (size_t)__ldg(&g_col[t])     * 32 + lane;
        size_t j1 = (size_t)__ldg(&g_col[t + 1]) * 32 + lane;
        uint4 h0 = __ldg(&hv[j0]);
        uint4 l0 = __ldg(&lv[j0]);
        uint4 h1 = __ldg(&hv[j1]);
        uint4 l1 = __ldg(&lv[j1]);
        const unsigned* p0h = (const unsigned*)&h0;
        const unsigned* p0l = (const unsigned*)&l0;
        const unsigned* p1h = (const unsigned*)&h1;
        const unsigned* p1l = (const unsigned*)&l1;
#pragma unroll
        for (int p = 0; p < 4; p++) {
            float2 a = __bfloat1622float2(*(const __nv_bfloat162*)&p0h[p]);
            float2 b = __bfloat1622float2(*(const __nv_bfloat162*)&p0l[p]);
            float2 c = __bfloat1622float2(*(const __nv_bfloat162*)&p1h[p]);
            float2 d = __bfloat1622float2(*(const __nv_bfloat162*)&p1l[p]);
            acc[p * 2]     += (a.x + b.x) + (c.x + d.x);
            acc[p * 2 + 1] += (a.y + b.y) + (c.y + d.y);
        }
    }
    if (t < e) {
        size_t j = (size_t)__ldg(&g_col[t]) * 32 + lane;
        uint4 h4 = __ldg(&hv[j]);
        uint4 l4 = __ldg(&lv[j]);
        const unsigned* hp = (const unsigned*)&h4;
        const unsigned* lp = (const unsigned*)&l4;
#pragma unroll
        for (int p = 0; p < 4; p++) {
            float2 fh = __bfloat1622float2(*(const __nv_bfloat162*)&hp[p]);
            float2 fl = __bfloat1622float2(*(const __nv_bfloat162*)&lp[p]);
            acc[p * 2]     += fh.x + fl.x;
            acc[p * 2 + 1] += fh.y + fl.y;
        }
    }
    float iv = g_inv[w];
    unsigned ho[4], lo[4];
#pragma unroll
    for (int p = 0; p < 4; p++)
        split2u(acc[p * 2] * iv, acc[p * 2 + 1] * iv, ho[p], lo[p]);
    ((uint4*)g_hiP[2])[(size_t)w * 32 + lane] = make_uint4(ho[0], ho[1], ho[2], ho[3]);
    ((uint4*)g_loP[2])[(size_t)w * 32 + lane] = make_uint4(lo[0], lo[1], lo[2], lo[3]);
}

// ---------------------------------------------------------------------------
// mma.sync bf16-split GEMM (R8 config: tile M=128 N=64, K chunks of 64).
//   LAYER=true : C = agg@Wl^T + h@Wr^T + bias, PReLU, write hi/lo planes.
//   LAYER=false: C = h@Wout^T + bias, write fp32 to Cext.
// 8 warps as 4(M) x 2(N); warp tile 32x32.
// Smem rows are 128B with 16B XOR swizzle (conflict-free LDSM).
// ---------------------------------------------------------------------------
static constexpr int SM_AHI = 0;
static constexpr int SM_ALO = 16384;
static constexpr int SM_WHI = 32768;
static constexpr int SM_WLO = 40960;
static constexpr int SMEM_TOTAL = 49152;

template <bool LAYER>
__global__ void __launch_bounds__(256)
gemm_mma(int selA2, int selOut, int ws1, int ws2,
         const float* __restrict__ bias, const float* __restrict__ slope,
         float* __restrict__ Cext, int n) {
    extern __shared__ __align__(16) char smem[];
    uint32_t sb = smem_to_u32(smem);
    int tid = threadIdx.x, wid = tid >> 5, lane = tid & 31;
    int warpM = wid & 3, warpN = wid >> 2;
    int m0 = blockIdx.x * 128, o0 = blockIdx.y * 64;

    float acc[2][4][4];
#pragma unroll
    for (int a = 0; a < 2; a++)
#pragma unroll
        for (int b = 0; b < 4; b++)
#pragma unroll
            for (int c = 0; c < 4; c++) acc[a][b][c] = 0.f;

    // ldmatrix lane addressing (constant per thread)
    int aRow = warpM * 32 + (lane & 15);
    int bRow = warpN * 32 + (lane & 15);
    int kbL  = (lane >> 4) * 16;          // 0 or 16 bytes (k half)
    uint32_t aXor = (uint32_t)((aRow & 7) << 4);
    uint32_t bXor = (uint32_t)((bRow & 7) << 4);

    const int NC = LAYER ? 8 : 4;
    for (int c = 0; c < NC; c++) {
        int op = LAYER ? (c >> 2) : 0;
        int kk = (c & 3) * 64;
        const __nv_bfloat16* Ah;
        const __nv_bfloat16* Al;
        if (LAYER && op == 0) { Ah = g_hiP[2];     Al = g_loP[2]; }
        else                  { Ah = g_hiP[selA2]; Al = g_loP[selA2]; }
        int ws = op ? ws2 : ws1;
        const __nv_bfloat16* Wh = (const __nv_bfloat16*)g_Whi + (size_t)ws * 65536;
        const __nv_bfloat16* Wl = (const __nv_bfloat16*)g_Wlo + (size_t)ws * 65536;

        __syncthreads();   // all warps done reading previous chunk's tiles
        // A tiles: 128 rows x 64 cols (128B/row) per plane
#pragma unroll
        for (int v = tid; v < 1024; v += 256) {
            int row = v >> 3, j = v & 7;
            int gr = min(m0 + row, n - 1);
            uint32_t so = (uint32_t)(row * 128 + ((j * 16) ^ ((row & 7) << 4)));
            size_t goff = (size_t)gr * D + kk + j * 8;
            *(uint4*)(smem + SM_AHI + so) = __ldg((const uint4*)(Ah + goff));
            *(uint4*)(smem + SM_ALO + so) = __ldg((const uint4*)(Al + goff));
        }
        // W tiles: 64 rows x 64 cols per plane
#pragma unroll
        for (int v = tid; v < 512; v += 256) {
            int row = v >> 3, j = v & 7;
            uint32_t so = (uint32_t)(row * 128 + ((j * 16) ^ ((row & 7) << 4)));
            size_t goff = (size_t)(o0 + row) * D + kk + j * 8;
            *(uint4*)(smem + SM_WHI + so) = __ldg((const uint4*)(Wh + goff));
            *(uint4*)(smem + SM_WLO + so) = __ldg((const uint4*)(Wl + goff));
        }
        __syncthreads();

        // 3 split products: (Ahi,Whi), (Ahi,Wlo), (Alo,Whi)
#pragma unroll
        for (int p = 0; p < 3; p++) {
            uint32_t aB = sb + (p == 2 ? SM_ALO : SM_AHI);
            uint32_t wB = sb + (p == 1 ? SM_WLO : SM_WHI);
#pragma unroll
            for (int k = 0; k < 4; k++) {
                uint32_t kb = (uint32_t)(k * 32 + kbL);
                uint32_t af[2][4], bf[2][4];
#pragma unroll
                for (int mt = 0; mt < 2; mt++)
                    ldsm4(aB + (uint32_t)((aRow + mt * 16) * 128) + (kb ^ aXor),
                          af[mt][0], af[mt][1], af[mt][2], af[mt][3]);
#pragma unroll
                for (int nt2 = 0; nt2 < 2; nt2++)
                    ldsm4(wB + (uint32_t)((bRow + nt2 * 16) * 128) + (kb ^ bXor),
                          bf[nt2][0], bf[nt2][1], bf[nt2][2], bf[nt2][3]);
#pragma unroll
                for (int mt = 0; mt < 2; mt++)
#pragma unroll
                    for (int nt2 = 0; nt2 < 2; nt2++) {
                        mma16816(acc[mt][nt2 * 2],
                                 af[mt][0], af[mt][1], af[mt][2], af[mt][3],
                                 bf[nt2][0], bf[nt2][2]);
                        mma16816(acc[mt][nt2 * 2 + 1],
                                 af[mt][0], af[mt][1], af[mt][2], af[mt][3],
                                 bf[nt2][1], bf[nt2][3]);
                    }
            }
        }
    }

    // ---- epilogue: direct stores from mma fragments ----
    int quad = lane >> 2, qt = lane & 3;
    float sl = LAYER ? __ldg(slope) : 0.f;
    float bj0[4], bj1[4];
#pragma unroll
    for (int nt = 0; nt < 4; nt++) {
        int col = o0 + warpN * 32 + nt * 8 + qt * 2;
        bj0[nt] = __ldg(&bias[col]);
        bj1[nt] = __ldg(&bias[col + 1]);
    }
#pragma unroll
    for (int mt = 0; mt < 2; mt++) {
#pragma unroll
        for (int half = 0; half < 2; half++) {
            int gr = m0 + warpM * 32 + mt * 16 + quad + half * 8;
            if (gr < n) {
#pragma unroll
                for (int nt = 0; nt < 4; nt++) {
                    float v0 = acc[mt][nt][half * 2]     + bj0[nt];
                    float v1 = acc[mt][nt][half * 2 + 1] + bj1[nt];
                    int cp = (o0 >> 1) + warpN * 16 + nt * 4 + qt;  // col pair idx
                    if (LAYER) {
                        v0 = (v0 >= 0.f) ? v0 : sl * v0;
                        v1 = (v1 >= 0.f) ? v1 : sl * v1;
                        unsigned hi, lo;
                        split2u(v0, v1, hi, lo);
                        size_t idx = (size_t)gr * 128 + cp;
                        ((unsigned*)g_hiP[selOut])[idx] = hi;
                        ((unsigned*)g_loP[selOut])[idx] = lo;
                    } else {
                        ((float2*)Cext)[(size_t)gr * 128 + cp] = make_float2(v0, v1);
                    }
                }
            }
        }
    }
}

// ---------------------------------------------------------------------------
// Host launcher
// Inputs: 0 x(i32,N) 1 edge_index(i32,2E) 2 edge_weight(unused) 3 emb
//         4 Wl1 5 bl1 6 Wr1 7 a1  8 Wl2 9 bl2 10 Wr2 11 a2
//         12 Wl3 13 bl3 14 Wr3 15 a3  16 Wout 17 bout
// ---------------------------------------------------------------------------
extern "C" void kernel_launch(void* const* d_in, const int* in_sizes, int n_in,
                              void* d_out, int out_size) {
    const int*   x   = (const int*)d_in[0];
    const int*   ei  = (const int*)d_in[1];
    const float* emb = (const float*)d_in[3];
    int n = in_sizes[0];
    int E = in_sizes[1] / 2;
    const int* src = ei;
    const int* dst = ei + E;

    const float* bl[3] = {(const float*)d_in[5], (const float*)d_in[9],  (const float*)d_in[13]};
    const float* ap[3] = {(const float*)d_in[7], (const float*)d_in[11], (const float*)d_in[15]};
    const float* bout  = (const float*)d_in[17];

    cudaFuncSetAttribute(gemm_mma<true>,  cudaFuncAttributeMaxDynamicSharedMemorySize, SMEM_TOTAL);
    cudaFuncSetAttribute(gemm_mma<false>, cudaFuncAttributeMaxDynamicSharedMemorySize, SMEM_TOTAL);

    // weight slots: 0..2 = Wl1..3, 3..5 = Wr1..3, 6 = Wout
    WPtrs wp;
    wp.p[0] = (const float*)d_in[4];
    wp.p[1] = (const float*)d_in[8];
    wp.p[2] = (const float*)d_in[12];
    wp.p[3] = (const float*)d_in[6];
    wp.p[4] = (const float*)d_in[10];
    wp.p[5] = (const float*)d_in[14];
    wp.p[6] = (const float*)d_in[16];
    convert_w<<<896, 256>>>(wp);

    // CSR build (parallel 3-phase scan)
    int nb = (n + 255) / 256;
    zero_deg<<<nb, 256>>>(n);
    count_deg<<<(E + 255) / 256, 256>>>(dst, E);
    block_sums<<<nb, 256>>>(n);
    scan_bsums<<<1, 1024>>>(nb, n, E);
    fill_row<<<nb, 256>>>(n);
    fill_csr<<<(E + 255) / 256, 256>>>(src, dst, E);

    // h0 = emb[x] -> planes 0
    gather_emb<<<(n * 32 + 255) / 256, 256>>>(x, emb, n);

    dim3 gg((n + 127) / 128, 4);
    int h = 0, o = 1;
    for (int l = 0; l < 3; l++) {
        aggregate<<<((size_t)n * 32 + 255) / 256, 256>>>(h, n);
        gemm_mma<true><<<gg, 256, SMEM_TOTAL>>>(h, o, l, 3 + l, bl[l], ap[l], nullptr, n);
        int t = h; h = o; o = t;
    }
    gemm_mma<false><<<gg, 256, SMEM_TOTAL>>>(h, 0, 6, 0, bout, nullptr, (float*)d_out, n);
}

// round 17
// speedup vs baseline: 1.3488x; 1.2188x over previous
#include <cuda_runtime.h>
#include <cuda_bf16.h>
#include <cstdint>

// ---------------------------------------------------------------------------
// GraphSAGE on GB300 (base sm_103 target: no tcgen05) —
// bf16-split mma.sync GEMM + CSR mean aggregation.
//
//   h kept as bf16 hi/lo plane pairs (hi+lo ~= fp32, err ~2^-18).
//   GEMM: mma.sync.m16n8k16 bf16, fp32 accum, 3-product split
//         (hi*hi + hi*lo + lo*hi), dual operand fused as K-chunk loop.
//   R11: aggregation reads the hi plane ONLY (halves the dominant gather
//   traffic; mean-of-32 bf16 roundings concentrate to ~2e-4 L2-norm error,
//   well under the 1e-3 budget). Mean still fp32-accumulated, re-split.
//   R12: identical resubmit (prior bench was an infra failure).
// ---------------------------------------------------------------------------

#define NMAX 100032
#define EMAX 3200000
#define D    256

// ---- static device scratch (no runtime allocation) ----
__device__ __align__(16) __nv_bfloat16 g_hiP[3][(size_t)NMAX * D];  // 0,1 = h ping-pong, 2 = agg
__device__ __align__(16) __nv_bfloat16 g_loP[3][(size_t)NMAX * D];
__device__ __align__(16) unsigned g_Whi[7 * 32768];   // 7 weight mats as bf16x2
__device__ __align__(16) unsigned g_Wlo[7 * 32768];
__device__ int   g_deg[NMAX];
__device__ int   g_rowptr[NMAX + 1];
__device__ int   g_cursor[NMAX];
__device__ float g_inv[NMAX];
__device__ int   g_col[EMAX];
__device__ int   g_bsum[1024];
__device__ int   g_boff[1024];

// ---------------------------------------------------------------------------
// helpers
// ---------------------------------------------------------------------------
__device__ __forceinline__ uint32_t smem_to_u32(const void* p) {
    uint32_t a;
    asm("{ .reg .u64 t; cvta.to.shared.u64 t, %1; cvt.u32.u64 %0, t; }"
        : "=r"(a) : "l"(p));
    return a;
}

__device__ __forceinline__ void ldsm4(uint32_t addr, uint32_t& r0, uint32_t& r1,
                                      uint32_t& r2, uint32_t& r3) {
    asm volatile("ldmatrix.sync.aligned.m8n8.x4.shared.b16 {%0,%1,%2,%3}, [%4];"
                 : "=r"(r0), "=r"(r1), "=r"(r2), "=r"(r3) : "r"(addr));
}

__device__ __forceinline__ void mma16816(float* c, uint32_t a0, uint32_t a1,
                                         uint32_t a2, uint32_t a3,
                                         uint32_t b0, uint32_t b1) {
    asm volatile(
        "mma.sync.aligned.m16n8k16.row.col.f32.bf16.bf16.f32 "
        "{%0,%1,%2,%3}, {%4,%5,%6,%7}, {%8,%9}, {%0,%1,%2,%3};"
        : "+f"(c[0]), "+f"(c[1]), "+f"(c[2]), "+f"(c[3])
        : "r"(a0), "r"(a1), "r"(a2), "r"(a3), "r"(b0), "r"(b1));
}

// split one fp32 pair into bf16x2 hi + bf16x2 lo
__device__ __forceinline__ void split2u(float a, float b, unsigned& hi, unsigned& lo) {
    __nv_bfloat162 h = __floats2bfloat162_rn(a, b);
    float2 hf = __bfloat1622float2(h);
    __nv_bfloat162 l = __floats2bfloat162_rn(a - hf.x, b - hf.y);
    hi = *reinterpret_cast<unsigned*>(&h);
    lo = *reinterpret_cast<unsigned*>(&l);
}

// ---------------------------------------------------------------------------
// CSR construction
// ---------------------------------------------------------------------------
__global__ void zero_deg(int n) {
    int i = blockIdx.x * blockDim.x + threadIdx.x;
    if (i < n) g_deg[i] = 0;
}

__global__ void count_deg(const int* __restrict__ dst, int E) {
    int i = blockIdx.x * blockDim.x + threadIdx.x;
    if (i < E) atomicAdd(&g_deg[dst[i]], 1);
}

__global__ void block_sums(int n) {
    int i = blockIdx.x * 256 + threadIdx.x;
    int v = (i < n) ? g_deg[i] : 0;
#pragma unroll
    for (int off = 16; off > 0; off >>= 1)
        v += __shfl_down_sync(0xFFFFFFFF, v, off);
    __shared__ int ws[8];
    int lane = threadIdx.x & 31, warp = threadIdx.x >> 5;
    if (lane == 0) ws[warp] = v;
    __syncthreads();
    if (threadIdx.x == 0) {
        int s = 0;
#pragma unroll
        for (int w = 0; w < 8; w++) s += ws[w];
        g_bsum[blockIdx.x] = s;
    }
}

__global__ void scan_bsums(int nb, int n, int E) {
    __shared__ int s[1024];
    int t = threadIdx.x;
    int v = (t < nb) ? g_bsum[t] : 0;
    s[t] = v;
    __syncthreads();
    for (int off = 1; off < 1024; off <<= 1) {
        int u = (t >= off) ? s[t - off] : 0;
        __syncthreads();
        s[t] += u;
        __syncthreads();
    }
    g_boff[t] = s[t] - v;   // exclusive
    if (t == 0) g_rowptr[n] = E;
}

__global__ void fill_row(int n) {
    int i = blockIdx.x * 256 + threadIdx.x;
    int lane = threadIdx.x & 31, warp = threadIdx.x >> 5;
    int d = (i < n) ? g_deg[i] : 0;
    int inc = d;
#pragma unroll
    for (int off = 1; off < 32; off <<= 1) {
        int u = __shfl_up_sync(0xFFFFFFFF, inc, off);
        if (lane >= off) inc += u;
    }
    __shared__ int wsum[8];
    if (lane == 31) wsum[warp] = inc;
    __syncthreads();
    int wbase = 0;
#pragma unroll
    for (int w = 0; w < 8; w++)
        if (w < warp) wbase += wsum[w];
    int ex = g_boff[blockIdx.x] + wbase + inc - d;
    if (i < n) {
        g_rowptr[i] = ex;
        g_cursor[i] = ex;
        g_inv[i]    = 1.0f / (float)max(d, 1);
    }
}

__global__ void fill_csr(const int* __restrict__ src,
                         const int* __restrict__ dst, int E) {
    int i = blockIdx.x * blockDim.x + threadIdx.x;
    if (i < E) {
        int d = dst[i];
        int p = atomicAdd(&g_cursor[d], 1);
        g_col[p] = src[i];
    }
}

// ---------------------------------------------------------------------------
// Weight conversion: 7 fp32 [256,256] matrices -> bf16 hi/lo planes
// ---------------------------------------------------------------------------
struct WPtrs { const float* p[7]; };

__global__ void convert_w(WPtrs wp) {
    int i = blockIdx.x * blockDim.x + threadIdx.x;
    if (i >= 7 * 32768) return;
    int w = i >> 15;
    int e = (i & 32767) * 2;
    const float* src = wp.p[w];
    unsigned hi, lo;
    split2u(__ldg(&src[e]), __ldg(&src[e + 1]), hi, lo);
    g_Whi[i] = hi;
    g_Wlo[i] = lo;
}

// ---------------------------------------------------------------------------
// h0 = emb[x] -> hi/lo planes of buffer 0
// ---------------------------------------------------------------------------
__global__ void gather_emb(const int* __restrict__ x,
                           const float* __restrict__ emb, int n) {
    int i = blockIdx.x * blockDim.x + threadIdx.x;
    if (i >= n * 32) return;
    int node = i >> 5, q = i & 31;
    const float4* src = (const float4*)(emb + (size_t)__ldg(&x[node]) * D) + q * 2;
    float4 f0 = __ldg(src), f1 = __ldg(src + 1);
    unsigned h0, l0, h1, l1, h2, l2, h3, l3;
    split2u(f0.x, f0.y, h0, l0); split2u(f0.z, f0.w, h1, l1);
    split2u(f1.x, f1.y, h2, l2); split2u(f1.z, f1.w, h3, l3);
    ((uint4*)g_hiP[0])[(size_t)node * 32 + q] = make_uint4(h0, h1, h2, h3);
    ((uint4*)g_loP[0])[(size_t)node * 32 + q] = make_uint4(l0, l1, l2, l3);
}

// ---------------------------------------------------------------------------
// Mean aggregation: warp per node, fp32 register accum.
// Reads hi plane ONLY (halves gather traffic; mean error ~2e-4 L2-norm).
// Edge loop unrolled x4 (4 independent 16B loads in flight per lane).
// ---------------------------------------------------------------------------
__device__ __forceinline__ void acc_hi4(float* acc, const uint4& h4) {
    const unsigned* hp = (const unsigned*)&h4;
#pragma unroll
    for (int p = 0; p < 4; p++) {
        float2 f = __bfloat1622float2(*(const __nv_bfloat162*)&hp[p]);
        acc[p * 2]     += f.x;
        acc[p * 2 + 1] += f.y;
    }
}

__global__ void __launch_bounds__(256)
aggregate(int selH, int n) {
    int w = (blockIdx.x * blockDim.x + threadIdx.x) >> 5;
    if (w >= n) return;
    int lane = threadIdx.x & 31;
    const uint4* hv = (const uint4*)g_hiP[selH];
    int s = g_rowptr[w], e = g_rowptr[w + 1];
    float acc[8] = {0.f, 0.f, 0.f, 0.f, 0.f, 0.f, 0.f, 0.f};
    int t = s;
    for (; t + 4 <= e; t += 4) {
        size_t j0 = (size_t)__ldg(&g_col[t])     * 32 + lane;
        size_t j1 = (size_t)__ldg(&g_col[t + 1]) * 32 + lane;
        size_t j2 = (size_t)__ldg(&g_col[t + 2]) * 32 + lane;
        size_t j3 = (size_t)__ldg(&g_col[t + 3]) * 32 + lane;
        uint4 h0 = __ldg(&hv[j0]);
        uint4 h1 = __ldg(&hv[j1]);
        uint4 h2 = __ldg(&hv[j2]);
        uint4 h3 = __ldg(&hv[j3]);
        acc_hi4(acc, h0);
        acc_hi4(acc, h1);
        acc_hi4(acc, h2);
        acc_hi4(acc, h3);
    }
    for (; t < e; t++) {
        size_t j = (size_t)__ldg(&g_col[t]) * 32 + lane;
        uint4 h4 = __ldg(&hv[j]);
        acc_hi4(acc, h4);
    }
    float iv = g_inv[w];
    unsigned ho[4], lo[4];
#pragma unroll
    for (int p = 0; p < 4; p++)
        split2u(acc[p * 2] * iv, acc[p * 2 + 1] * iv, ho[p], lo[p]);
    ((uint4*)g_hiP[2])[(size_t)w * 32 + lane] = make_uint4(ho[0], ho[1], ho[2], ho[3]);
    ((uint4*)g_loP[2])[(size_t)w * 32 + lane] = make_uint4(lo[0], lo[1], lo[2], lo[3]);
}

// ---------------------------------------------------------------------------
// mma.sync bf16-split GEMM (tile M=128 N=64, K chunks of 64).
//   LAYER=true : C = agg@Wl^T + h@Wr^T + bias, PReLU, write hi/lo planes.
//   LAYER=false: C = h@Wout^T + bias, write fp32 to Cext.
// 8 warps as 4(M) x 2(N); warp tile 32x32.
// Smem rows are 128B with 16B XOR swizzle (conflict-free LDSM).
// ---------------------------------------------------------------------------
static constexpr int SM_AHI = 0;
static constexpr int SM_ALO = 16384;
static constexpr int SM_WHI = 32768;
static constexpr int SM_WLO = 40960;
static constexpr int SMEM_TOTAL = 49152;

template <bool LAYER>
__global__ void __launch_bounds__(256)
gemm_mma(int selA2, int selOut, int ws1, int ws2,
         const float* __restrict__ bias, const float* __restrict__ slope,
         float* __restrict__ Cext, int n) {
    extern __shared__ __align__(16) char smem[];
    uint32_t sb = smem_to_u32(smem);
    int tid = threadIdx.x, wid = tid >> 5, lane = tid & 31;
    int warpM = wid & 3, warpN = wid >> 2;
    int m0 = blockIdx.x * 128, o0 = blockIdx.y * 64;

    float acc[2][4][4];
#pragma unroll
    for (int a = 0; a < 2; a++)
#pragma unroll
        for (int b = 0; b < 4; b++)
#pragma unroll
            for (int c = 0; c < 4; c++) acc[a][b][c] = 0.f;

    // ldmatrix lane addressing (constant per thread)
    int aRow = warpM * 32 + (lane & 15);
    int bRow = warpN * 32 + (lane & 15);
    int kbL  = (lane >> 4) * 16;          // 0 or 16 bytes (k half)
    uint32_t aXor = (uint32_t)((aRow & 7) << 4);
    uint32_t bXor = (uint32_t)((bRow & 7) << 4);

    const int NC = LAYER ? 8 : 4;
    for (int c = 0; c < NC; c++) {
        int op = LAYER ? (c >> 2) : 0;
        int kk = (c & 3) * 64;
        const __nv_bfloat16* Ah;
        const __nv_bfloat16* Al;
        if (LAYER && op == 0) { Ah = g_hiP[2];     Al = g_loP[2]; }
        else                  { Ah = g_hiP[selA2]; Al = g_loP[selA2]; }
        int ws = op ? ws2 : ws1;
        const __nv_bfloat16* Wh = (const __nv_bfloat16*)g_Whi + (size_t)ws * 65536;
        const __nv_bfloat16* Wl = (const __nv_bfloat16*)g_Wlo + (size_t)ws * 65536;

        __syncthreads();   // all warps done reading previous chunk's tiles
        // A tiles: 128 rows x 64 cols (128B/row) per plane
#pragma unroll
        for (int v = tid; v < 1024; v += 256) {
            int row = v >> 3, j = v & 7;
            int gr = min(m0 + row, n - 1);
            uint32_t so = (uint32_t)(row * 128 + ((j * 16) ^ ((row & 7) << 4)));
            size_t goff = (size_t)gr * D + kk + j * 8;
            *(uint4*)(smem + SM_AHI + so) = __ldg((const uint4*)(Ah + goff));
            *(uint4*)(smem + SM_ALO + so) = __ldg((const uint4*)(Al + goff));
        }
        // W tiles: 64 rows x 64 cols per plane
#pragma unroll
        for (int v = tid; v < 512; v += 256) {
            int row = v >> 3, j = v & 7;
            uint32_t so = (uint32_t)(row * 128 + ((j * 16) ^ ((row & 7) << 4)));
            size_t goff = (size_t)(o0 + row) * D + kk + j * 8;
            *(uint4*)(smem + SM_WHI + so) = __ldg((const uint4*)(Wh + goff));
            *(uint4*)(smem + SM_WLO + so) = __ldg((const uint4*)(Wl + goff));
        }
        __syncthreads();

        // 3 split products: (Ahi,Whi), (Ahi,Wlo), (Alo,Whi)
#pragma unroll
        for (int p = 0; p < 3; p++) {
            uint32_t aB = sb + (p == 2 ? SM_ALO : SM_AHI);
            uint32_t wB = sb + (p == 1 ? SM_WLO : SM_WHI);
#pragma unroll
            for (int k = 0; k < 4; k++) {
                uint32_t kb = (uint32_t)(k * 32 + kbL);
                uint32_t af[2][4], bf[2][4];
#pragma unroll
                for (int mt = 0; mt < 2; mt++)
                    ldsm4(aB + (uint32_t)((aRow + mt * 16) * 128) + (kb ^ aXor),
                          af[mt][0], af[mt][1], af[mt][2], af[mt][3]);
#pragma unroll
                for (int nt2 = 0; nt2 < 2; nt2++)
                    ldsm4(wB + (uint32_t)((bRow + nt2 * 16) * 128) + (kb ^ bXor),
                          bf[nt2][0], bf[nt2][1], bf[nt2][2], bf[nt2][3]);
#pragma unroll
                for (int mt = 0; mt < 2; mt++)
#pragma unroll
                    for (int nt2 = 0; nt2 < 2; nt2++) {
                        mma16816(acc[mt][nt2 * 2],
                                 af[mt][0], af[mt][1], af[mt][2], af[mt][3],
                                 bf[nt2][0], bf[nt2][2]);
                        mma16816(acc[mt][nt2 * 2 + 1],
                                 af[mt][0], af[mt][1], af[mt][2], af[mt][3],
                                 bf[nt2][1], bf[nt2][3]);
                    }
            }
        }
    }

    // ---- epilogue: direct stores from mma fragments ----
    int quad = lane >> 2, qt = lane & 3;
    float sl = LAYER ? __ldg(slope) : 0.f;
    float bj0[4], bj1[4];
#pragma unroll
    for (int nt = 0; nt < 4; nt++) {
        int col = o0 + warpN * 32 + nt * 8 + qt * 2;
        bj0[nt] = __ldg(&bias[col]);
        bj1[nt] = __ldg(&bias[col + 1]);
    }
#pragma unroll
    for (int mt = 0; mt < 2; mt++) {
#pragma unroll
        for (int half = 0; half < 2; half++) {
            int gr = m0 + warpM * 32 + mt * 16 + quad + half * 8;
            if (gr < n) {
#pragma unroll
                for (int nt = 0; nt < 4; nt++) {
                    float v0 = acc[mt][nt][half * 2]     + bj0[nt];
                    float v1 = acc[mt][nt][half * 2 + 1] + bj1[nt];
                    int cp = (o0 >> 1) + warpN * 16 + nt * 4 + qt;  // col pair idx
                    if (LAYER) {
                        v0 = (v0 >= 0.f) ? v0 : sl * v0;
                        v1 = (v1 >= 0.f) ? v1 : sl * v1;
                        unsigned hi, lo;
                        split2u(v0, v1, hi, lo);
                        size_t idx = (size_t)gr * 128 + cp;
                        ((unsigned*)g_hiP[selOut])[idx] = hi;
                        ((unsigned*)g_loP[selOut])[idx] = lo;
                    } else {
                        ((float2*)Cext)[(size_t)gr * 128 + cp] = make_float2(v0, v1);
                    }
                }
            }
        }
    }
}

// ---------------------------------------------------------------------------
// Host launcher
// Inputs: 0 x(i32,N) 1 edge_index(i32,2E) 2 edge_weight(unused) 3 emb
//         4 Wl1 5 bl1 6 Wr1 7 a1  8 Wl2 9 bl2 10 Wr2 11 a2
//         12 Wl3 13 bl3 14 Wr3 15 a3  16 Wout 17 bout
// ---------------------------------------------------------------------------
extern "C" void kernel_launch(void* const* d_in, const int* in_sizes, int n_in,
                              void* d_out, int out_size) {
    const int*   x   = (const int*)d_in[0];
    const int*   ei  = (const int*)d_in[1];
    const float* emb = (const float*)d_in[3];
    int n = in_sizes[0];
    int E = in_sizes[1] / 2;
    const int* src = ei;
    const int* dst = ei + E;

    const float* bl[3] = {(const float*)d_in[5], (const float*)d_in[9],  (const float*)d_in[13]};
    const float* ap[3] = {(const float*)d_in[7], (const float*)d_in[11], (const float*)d_in[15]};
    const float* bout  = (const float*)d_in[17];

    cudaFuncSetAttribute(gemm_mma<true>,  cudaFuncAttributeMaxDynamicSharedMemorySize, SMEM_TOTAL);
    cudaFuncSetAttribute(gemm_mma<false>, cudaFuncAttributeMaxDynamicSharedMemorySize, SMEM_TOTAL);

    // weight slots: 0..2 = Wl1..3, 3..5 = Wr1..3, 6 = Wout
    WPtrs wp;
    wp.p[0] = (const float*)d_in[4];
    wp.p[1] = (const float*)d_in[8];
    wp.p[2] = (const float*)d_in[12];
    wp.p[3] = (const float*)d_in[6];
    wp.p[4] = (const float*)d_in[10];
    wp.p[5] = (const float*)d_in[14];
    wp.p[6] = (const float*)d_in[16];
    convert_w<<<896, 256>>>(wp);

    // CSR build (parallel 3-phase scan)
    int nb = (n + 255) / 256;
    zero_deg<<<nb, 256>>>(n);
    count_deg<<<(E + 255) / 256, 256>>>(dst, E);
    block_sums<<<nb, 256>>>(n);
    scan_bsums<<<1, 1024>>>(nb, n, E);
    fill_row<<<nb, 256>>>(n);
    fill_csr<<<(E + 255) / 256, 256>>>(src, dst, E);

    // h0 = emb[x] -> planes 0
    gather_emb<<<(n * 32 + 255) / 256, 256>>>(x, emb, n);

    dim3 gg((n + 127) / 128, 4);
    int h = 0, o = 1;
    for (int l = 0; l < 3; l++) {
        aggregate<<<((size_t)n * 32 + 255) / 256, 256>>>(h, n);
        gemm_mma<true><<<gg, 256, SMEM_TOTAL>>>(h, o, l, 3 + l, bl[l], ap[l], nullptr, n);
        int t = h; h = o; o = t;
    }
    gemm_mma<false><<<gg, 256, SMEM_TOTAL>>>(h, 0, 6, 0, bout, nullptr, (float*)d_out, n);
}